// round 3
// baseline (speedup 1.0000x reference)
#include <cuda_runtime.h>

// Gray-Scott residual, float4-vectorized smem ring version.
// Input: output (50,2,100,100,100) fp32. Output: f_u(48,96,96,96) ++ f_v.
//
// Block = (24 z-quad threads, 8 x rows) = 192 threads, covers full z (96 out)
// and 8 x rows; marches y. 3-slot smem plane ring (planes y+2..y+4); y-taps
// and centers held in a 5-deep float4 register ring.
// smem column = z_in + 2 so all compute LDS are 16B-aligned LDS.128.

#define TOUT 48
#define D 96
#define IN_T 2000000
#define IN_C 1000000
#define IN_Y 10000
#define IN_X 100
#define N_OUT (TOUT * D * D * D)

#define ZQ 24          // z-quad threads (24*4 = 96 outputs, full z)
#define BXO 8          // output x rows per block
#define TILE_X 12      // BXO + 4 halo
#define ROW_F 104      // smem row width (cols 2..101 hold z_in 0..99)
#define NQ 25          // gmem float4 quads per input row
#define QTOT (TILE_X * NQ)   // 300 quads per channel per plane
#define NTHR 192

__global__ void __launch_bounds__(192) gs_kernel(
    const float* __restrict__ in, float* __restrict__ out)
{
    __shared__ float su[3][TILE_X][ROW_F];
    __shared__ float sv[3][TILE_X][ROW_F];

    const int tzq = threadIdx.x;       // 0..23
    const int tx  = threadIdx.y;       // 0..7
    const int tid = tx * ZQ + tzq;

    const int x0 = blockIdx.x * BXO;   // input x tile origin
    const int t  = blockIdx.y;

    const float* bu = in + t * IN_T + x0 * IN_X;

    // ---- loader precompute (2 strided passes over 300 quads/channel) ----
    const int r0 = tid / NQ, q0 = tid % NQ;
    const int i1 = tid + NTHR;
    const bool vld1 = (i1 < QTOT);
    const int r1 = vld1 ? i1 / NQ : 0, q1 = vld1 ? i1 % NQ : 0;
    const int g0 = r0 * IN_X + 4 * q0;
    const int g1 = r1 * IN_X + 4 * q1;
    const int sc0 = 4 * q0 + 2;        // shifted smem col
    const int sc1 = 4 * q1 + 2;

    auto load_plane = [&](int y_in, int s) {
        const float* pu = bu + y_in * IN_Y;
        {
            float4 a = __ldg((const float4*)(pu + g0));
            *(float2*)&su[s][r0][sc0]     = make_float2(a.x, a.y);
            *(float2*)&su[s][r0][sc0 + 2] = make_float2(a.z, a.w);
            float4 b = __ldg((const float4*)(pu + IN_C + g0));
            *(float2*)&sv[s][r0][sc0]     = make_float2(b.x, b.y);
            *(float2*)&sv[s][r0][sc0 + 2] = make_float2(b.z, b.w);
        }
        if (vld1) {
            float4 a = __ldg((const float4*)(pu + g1));
            *(float2*)&su[s][r1][sc1]     = make_float2(a.x, a.y);
            *(float2*)&su[s][r1][sc1 + 2] = make_float2(a.z, a.w);
            float4 b = __ldg((const float4*)(pu + IN_C + g1));
            *(float2*)&sv[s][r1][sc1]     = make_float2(b.x, b.y);
            *(float2*)&sv[s][r1][sc1 + 2] = make_float2(b.z, b.w);
        }
    };

    const int xc  = tx + 2;            // this thread's center smem row
    const int cz0 = 4 * tzq;           // z-window base col (z_in 4k-2)
    const int czc = cz0 + 4;           // center quad col (z_in 2+4k..5+4k)

    // ---- prologue: planes 0..3, register ring of center quads ----
    load_plane(0, 0); load_plane(1, 1); load_plane(2, 2);
    __syncthreads();

    float ru0[4], ru1[4], ru2[4], ru3[4], ru4[4];
    float rv0[4], rv1[4], rv2[4], rv3[4], rv4[4];
    *(float4*)ru0 = *(const float4*)&su[0][xc][czc];
    *(float4*)rv0 = *(const float4*)&sv[0][xc][czc];
    *(float4*)ru1 = *(const float4*)&su[1][xc][czc];
    *(float4*)rv1 = *(const float4*)&sv[1][xc][czc];
    *(float4*)ru2 = *(const float4*)&su[2][xc][czc];
    *(float4*)rv2 = *(const float4*)&sv[2][xc][czc];
    __syncthreads();
    load_plane(3, 0);                  // plane 3 -> slot 0 (plane 0 only needed in ring)
    __syncthreads();
    *(float4*)ru3 = *(const float4*)&su[0][xc][czc];
    *(float4*)rv3 = *(const float4*)&sv[0][xc][czc];

    // t+1 center pointer and output pointer
    const float* np0 = in + (t + 1) * IN_T + 2 * IN_Y + (x0 + tx + 2) * IN_X + cz0;
    float* ou = out + ((t * D) * D + (x0 + tx)) * D + cz0;

    const float INV_DX2 = 2304.0f / 10000.0f;
    const float C1 = 4.0f / 3.0f;
    const float C2 = -1.0f / 12.0f;
    const float C0 = -7.5f;

    int sn = 1, sc = 2;                // slot of plane y+4 (to load), plane y+2 (center)

    #pragma unroll 1
    for (int y = 0; y < D; y++) {
        __syncthreads();               // all reads of slot sn (plane y+1) done
        load_plane(y + 4, sn);
        __syncthreads();

        *(float4*)ru4 = *(const float4*)&su[sn][xc][czc];
        *(float4*)rv4 = *(const float4*)&sv[sn][xc][czc];

        // z-window (12 floats = z_in 4k-2 .. 4k+9) and x-taps (center quads)
        float zu[12], zv[12];
        *(float4*)&zu[0] = *(const float4*)&su[sc][xc][cz0];
        *(float4*)&zu[4] = *(const float4*)&su[sc][xc][cz0 + 4];
        *(float4*)&zu[8] = *(const float4*)&su[sc][xc][cz0 + 8];
        *(float4*)&zv[0] = *(const float4*)&sv[sc][xc][cz0];
        *(float4*)&zv[4] = *(const float4*)&sv[sc][xc][cz0 + 4];
        *(float4*)&zv[8] = *(const float4*)&sv[sc][xc][cz0 + 8];

        float um1[4], up1[4], um2[4], up2[4];
        float vm1[4], vp1[4], vm2[4], vp2[4];
        *(float4*)um1 = *(const float4*)&su[sc][xc - 1][czc];
        *(float4*)up1 = *(const float4*)&su[sc][xc + 1][czc];
        *(float4*)um2 = *(const float4*)&su[sc][xc - 2][czc];
        *(float4*)up2 = *(const float4*)&su[sc][xc + 2][czc];
        *(float4*)vm1 = *(const float4*)&sv[sc][xc - 1][czc];
        *(float4*)vp1 = *(const float4*)&sv[sc][xc + 1][czc];
        *(float4*)vm2 = *(const float4*)&sv[sc][xc - 2][czc];
        *(float4*)vp2 = *(const float4*)&sv[sc][xc + 2][czc];

        // t+1 centers: two overlapping aligned quads per channel
        const float* np = np0 + y * IN_Y;
        float4 a0 = __ldg((const float4*)np);
        float4 a1 = __ldg((const float4*)(np + 4));
        float4 b0 = __ldg((const float4*)(np + IN_C));
        float4 b1 = __ldg((const float4*)(np + IN_C + 4));
        float unx[4] = {a0.z, a0.w, a1.x, a1.y};
        float vnx[4] = {b0.z, b0.w, b1.x, b1.y};

        float fu[4], fv[4];
        #pragma unroll
        for (int j = 0; j < 4; j++) {
            float cu = zu[4 + j], cv = zv[4 + j];
            float s1u = zu[3 + j] + zu[5 + j] + um1[j] + up1[j] + ru1[j] + ru3[j];
            float s2u = zu[2 + j] + zu[6 + j] + um2[j] + up2[j] + ru0[j] + ru4[j];
            float s1v = zv[3 + j] + zv[5 + j] + vm1[j] + vp1[j] + rv1[j] + rv3[j];
            float s2v = zv[2 + j] + zv[6 + j] + vm2[j] + vp2[j] + rv0[j] + rv4[j];

            float lap_u = (C0 * cu + C1 * s1u + C2 * s2u) * INV_DX2;
            float lap_v = (C0 * cv + C1 * s1v + C2 * s2v) * INV_DX2;

            float u_t = (unx[j] - cu) * 2.0f;
            float v_t = (vnx[j] - cv) * 2.0f;
            float uv2 = cu * cv * cv;

            fu[j] = 0.2f * lap_u - uv2 + 0.025f * (1.0f - cu) - u_t;
            fv[j] = 0.1f * lap_v + uv2 - 0.08f * cv - v_t;
        }

        *(float4*)(ou + y * (D * D))         = *(float4*)fu;
        *(float4*)(ou + y * (D * D) + N_OUT) = *(float4*)fv;

        // rotate register ring
        #pragma unroll
        for (int m = 0; m < 4; m++) {
            ru0[m] = ru1[m]; ru1[m] = ru2[m]; ru2[m] = ru3[m]; ru3[m] = ru4[m];
            rv0[m] = rv1[m]; rv1[m] = rv2[m]; rv2[m] = rv3[m]; rv3[m] = rv4[m];
        }

        // advance ring slots: sn <- sc, sc <- sc+1 (mod 3)
        sn = sc;
        sc = (sc == 2) ? 0 : sc + 1;
    }
}

extern "C" void kernel_launch(void* const* d_in, const int* in_sizes, int n_in,
                              void* d_out, int out_size)
{
    const float* in = (const float*)d_in[0];
    float* out = (float*)d_out;
    dim3 block(ZQ, BXO);               // (24, 8) = 192 threads
    dim3 grid(D / BXO, TOUT);          // (12, 48) = 576 blocks
    gs_kernel<<<grid, block>>>(in, out);
}

// round 4
// speedup vs baseline: 1.8349x; 1.8349x over previous
#include <cuda_runtime.h>

// Gray-Scott residual, 2 outputs/thread, aligned float2 gmem loads, no smem.
// Input: output (50,2,100,100,100) fp32. Output: f_u(48,96,96,96) ++ f_v.

#define TOUT 48
#define D 96
#define IN_T 2000000
#define IN_C 1000000
#define IN_Y 10000
#define IN_X 100
#define N_OUT (TOUT * D * D * D)       // 42467328
#define N_PAIR (N_OUT / 2)             // 21233664

__device__ __forceinline__ float2 ldg2(const float* p) {
    return __ldg((const float2*)p);
}

__global__ void __launch_bounds__(256) gs_kernel2(
    const float* __restrict__ in, float* __restrict__ out)
{
    int idx = blockIdx.x * 256 + threadIdx.x;
    if (idx >= N_PAIR) return;

    int zp = idx % (D / 2);            // z pair index: outputs z = 2zp, 2zp+1
    int r  = idx / (D / 2);
    int x  = r % D;
    r /= D;
    int y  = r % D;
    int t  = r / D;

    // input center of first output point: (t, c, y+2, x+2, 2zp+2)
    const int zi = 2 * zp;             // window base z_in (8B aligned)
    const float* up = in + t * IN_T + (y + 2) * IN_Y + (x + 2) * IN_X + (zi + 2);
    const float* vp = up + IN_C;

    // z-window: z_in [zi .. zi+5] as three aligned float2
    float2 uw0 = ldg2(up - 2), uw1 = ldg2(up), uw2 = ldg2(up + 2);
    float2 vw0 = ldg2(vp - 2), vw1 = ldg2(vp), vw2 = ldg2(vp + 2);

    // x taps (center z pair)
    float2 uxm1 = ldg2(up - IN_X),     uxp1 = ldg2(up + IN_X);
    float2 uxm2 = ldg2(up - 2 * IN_X), uxp2 = ldg2(up + 2 * IN_X);
    float2 vxm1 = ldg2(vp - IN_X),     vxp1 = ldg2(vp + IN_X);
    float2 vxm2 = ldg2(vp - 2 * IN_X), vxp2 = ldg2(vp + 2 * IN_X);

    // y taps
    float2 uym1 = ldg2(up - IN_Y),     uyp1 = ldg2(up + IN_Y);
    float2 uym2 = ldg2(up - 2 * IN_Y), uyp2 = ldg2(up + 2 * IN_Y);
    float2 vym1 = ldg2(vp - IN_Y),     vyp1 = ldg2(vp + IN_Y);
    float2 vym2 = ldg2(vp - 2 * IN_Y), vyp2 = ldg2(vp + 2 * IN_Y);

    // t+1 centers
    float2 un = ldg2(up + IN_T);
    float2 vn = ldg2(vp + IN_T);

    const float INV_DX2 = 2304.0f / 10000.0f;  // 1/DX^2
    const float C1 = 4.0f / 3.0f;
    const float C2 = -1.0f / 12.0f;
    const float C0 = -7.5f;

    // lane 0: center = w1.x ; z±1 = w0.y, w1.y ; z±2 = w0.x, w2.x
    // lane 1: center = w1.y ; z±1 = w1.x, w2.x ; z±2 = w0.y, w2.y
    float cu0 = uw1.x, cu1 = uw1.y, cv0 = vw1.x, cv1 = vw1.y;

    float s1u0 = uw0.y + uw1.y + uxm1.x + uxp1.x + uym1.x + uyp1.x;
    float s2u0 = uw0.x + uw2.x + uxm2.x + uxp2.x + uym2.x + uyp2.x;
    float s1u1 = uw1.x + uw2.x + uxm1.y + uxp1.y + uym1.y + uyp1.y;
    float s2u1 = uw0.y + uw2.y + uxm2.y + uxp2.y + uym2.y + uyp2.y;

    float s1v0 = vw0.y + vw1.y + vxm1.x + vxp1.x + vym1.x + vyp1.x;
    float s2v0 = vw0.x + vw2.x + vxm2.x + vxp2.x + vym2.x + vyp2.x;
    float s1v1 = vw1.x + vw2.x + vxm1.y + vxp1.y + vym1.y + vyp1.y;
    float s2v1 = vw0.y + vw2.y + vxm2.y + vxp2.y + vym2.y + vyp2.y;

    float lapu0 = (C0 * cu0 + C1 * s1u0 + C2 * s2u0) * INV_DX2;
    float lapu1 = (C0 * cu1 + C1 * s1u1 + C2 * s2u1) * INV_DX2;
    float lapv0 = (C0 * cv0 + C1 * s1v0 + C2 * s2v0) * INV_DX2;
    float lapv1 = (C0 * cv1 + C1 * s1v1 + C2 * s2v1) * INV_DX2;

    float uv20 = cu0 * cv0 * cv0;
    float uv21 = cu1 * cv1 * cv1;

    float2 fu, fv;
    fu.x = 0.2f * lapu0 - uv20 + 0.025f * (1.0f - cu0) - (un.x - cu0) * 2.0f;
    fu.y = 0.2f * lapu1 - uv21 + 0.025f * (1.0f - cu1) - (un.y - cu1) * 2.0f;
    fv.x = 0.1f * lapv0 + uv20 - 0.08f * cv0 - (vn.x - cv0) * 2.0f;
    fv.y = 0.1f * lapv1 + uv21 - 0.08f * cv1 - (vn.y - cv1) * 2.0f;

    // output index of first point
    int oidx = ((t * D + y) * D + x) * D + zi;
    *(float2*)(out + oidx)         = fu;
    *(float2*)(out + oidx + N_OUT) = fv;
}

extern "C" void kernel_launch(void* const* d_in, const int* in_sizes, int n_in,
                              void* d_out, int out_size)
{
    const float* in = (const float*)d_in[0];
    float* out = (float*)d_out;
    int blocks = (N_PAIR + 255) / 256;     // 82944
    gs_kernel2<<<blocks, 256>>>(in, out);
}